// round 6
// baseline (speedup 1.0000x reference)
#include <cuda_runtime.h>
#include <cstdint>

#define LROW     32768
#define NTHREADS 128
#define CHUNK    8
#define TILE     (NTHREADS * CHUNK)   // 1024
#define NTILES   (LROW / TILE)        // 32
#define CTAS     1184                 // 148 SMs x 8 CTAs, persistent

// ---- f32x2 packed helpers (sm_100+) ----
__device__ __forceinline__ uint64_t pack2(float lo, float hi) {
    uint64_t r; asm("mov.b64 %0, {%1, %2};" : "=l"(r) : "f"(lo), "f"(hi)); return r;
}
__device__ __forceinline__ uint64_t dup2(float v) { return pack2(v, v); }
__device__ __forceinline__ void unpack2(uint64_t v, float& lo, float& hi) {
    asm("mov.b64 {%0, %1}, %2;" : "=f"(lo), "=f"(hi) : "l"(v));
}
__device__ __forceinline__ uint64_t fma2(uint64_t a, uint64_t b, uint64_t c) {
    uint64_t d; asm("fma.rn.f32x2 %0, %1, %2, %3;" : "=l"(d) : "l"(a), "l"(b), "l"(c)); return d;
}
__device__ __forceinline__ uint64_t mul2(uint64_t a, uint64_t b) {
    uint64_t d; asm("mul.rn.f32x2 %0, %1, %2;" : "=l"(d) : "l"(a), "l"(b)); return d;
}

// Load window x[o-8 .. o+15] of one tile into 6 float4 regs (clamped at row edges).
__device__ __forceinline__ void load_window(float4 pf[6], const float* __restrict__ x,
                                            int tile)
{
    const int row = tile >> 5;                       // NTILES = 32
    const int o   = (tile & (NTILES - 1)) * TILE + threadIdx.x * CHUNK;
    const float* xr = x + (size_t)row * LROW;
    if ((o != 0) & (o != LROW - CHUNK)) {
        const float4* p = (const float4*)(xr + (o - 8));   // 16B aligned
#pragma unroll
        for (int v = 0; v < 6; ++v) pf[v] = __ldg(p + v);
    } else {
        float tmp[24];
#pragma unroll
        for (int j = 0; j < 24; ++j) {
            int gi = o - 8 + j;
            gi = max(0, min(gi, LROW - 1));
            tmp[j] = __ldg(xr + gi);
        }
#pragma unroll
        for (int v = 0; v < 6; ++v)
            pf[v] = make_float4(tmp[4*v], tmp[4*v+1], tmp[4*v+2], tmp[4*v+3]);
    }
}

// Fused up-2x (12-tap polyphase) -> LeakyReLU(0.1) -> down-2x, f32x2-packed,
// persistent + SOFTWARE-PIPELINED: next tile's window is prefetched into
// registers before computing the current tile, hiding DRAM latency per-warp.
__global__ __launch_bounds__(NTHREADS)
void aa_act_kernel(const float* __restrict__ x,
                   const float* __restrict__ upf,
                   const float* __restrict__ dnf,
                   float* __restrict__ out,
                   int total_tiles)
{
    // Packed taps (uniform, loaded once per CTA lifetime).
    uint64_t f2[6], dnp[6];
#pragma unroll
    for (int e = 0; e < 6; ++e)
        f2[e] = pack2(2.0f * __ldg(upf + 2 * e), 2.0f * __ldg(upf + 2 * e + 1));
#pragma unroll
    for (int m = 0; m < 6; ++m)
        dnp[m] = pack2(__ldg(dnf + 2 * m + 1), __ldg(dnf + 2 * m));
    const uint64_t c55 = dup2(0.55f), c45 = dup2(0.45f);

    int tile = blockIdx.x;
    if (tile >= total_tiles) return;

    float4 pf[6];
    load_window(pf, x, tile);                        // prologue prefetch

    for (; tile < total_tiles; tile += CTAS) {
        const int row = tile >> 5;
        const int o   = (tile & (NTILES - 1)) * TILE + threadIdx.x * CHUNK;

        // Consume prefetch -> lane-duplicated packs.
        uint64_t xx[24];
#pragma unroll
        for (int v = 0; v < 6; ++v) {
            float4 q = pf[v];
            xx[4 * v + 0] = dup2(q.x); xx[4 * v + 1] = dup2(q.y);
            xx[4 * v + 2] = dup2(q.z); xx[4 * v + 3] = dup2(q.w);
        }

        // Prefetch next tile (issued before compute; no dependency on it below).
        const int ntile = tile + CTAS;
        if (ntile < total_tiles) load_window(pf, x, ntile);

        // Up-sample + lrelu, packed.  EO[t] = (E[t], O[t]),
        //   E[t]==act[2*(o-2+t)], O[t]==act[2*(o-3+t)+1]; window xx[t+3 .. t+8].
        uint64_t EO[13];
#pragma unroll
        for (int t = 0; t < 13; ++t) {
            uint64_t v = mul2(f2[0], xx[t + 3]);
#pragma unroll
            for (int e = 1; e < 6; ++e)
                v = fma2(f2[e], xx[t + 3 + e], v);
            uint64_t av = v & 0x7FFFFFFF7FFFFFFFULL;      // packed |v|
            EO[t] = fma2(c45, av, mul2(c55, v));          // packed lrelu
        }

        // Row-edge act-index fixups (act index clamps to act[0] / act[2L-1]).
        if (o == 0) {
            float a0 = __uint_as_float((uint32_t)EO[2]);          // E[2]==act[0]
            uint64_t p = dup2(a0);
            EO[0] = p; EO[1] = p; EO[2] = p;
        }
        if (o == LROW - CHUNK) {
            float aL = __uint_as_float((uint32_t)(EO[10] >> 32)); // O[10]==act[2L-1]
            uint64_t p = dup2(aL);
            EO[10] = p; EO[11] = p; EO[12] = p;
        }

        // Downsample: out[o+q] = sum_m dn[2m]*O[q+m] + dn[2m+1]*E[q+m]
        float acc[CHUNK];
#pragma unroll
        for (int q = 0; q < CHUNK; ++q) {
            uint64_t a2 = mul2(dnp[0], EO[q]);
#pragma unroll
            for (int m = 1; m < 6; ++m)
                a2 = fma2(dnp[m], EO[q + m], a2);
            float lo, hi; unpack2(a2, lo, hi);
            acc[q] = lo + hi;
        }

        float4* op = (float4*)(out + (size_t)row * LROW + o);
        op[0] = make_float4(acc[0], acc[1], acc[2], acc[3]);
        op[1] = make_float4(acc[4], acc[5], acc[6], acc[7]);
    }
}

extern "C" void kernel_launch(void* const* d_in, const int* in_sizes, int n_in,
                              void* d_out, int out_size)
{
    const float* x   = (const float*)d_in[0];
    const float* upf = (const float*)d_in[1];
    const float* dnf = (const float*)d_in[2];
    float* out = (float*)d_out;

    const int rows = in_sizes[0] / LROW;           // 8*128 = 1024
    const int total_tiles = rows * NTILES;         // 32768
    aa_act_kernel<<<CTAS, NTHREADS>>>(x, upf, dnf, out, total_tiles);
}

// round 7
// speedup vs baseline: 1.1752x; 1.1752x over previous
#include <cuda_runtime.h>
#include <cstdint>

#define LROW     32768
#define NTHREADS 128
#define CHUNK    8
#define TILE     1024                 // NTHREADS * CHUNK
#define NTILES   32                   // LROW / TILE
#define OCC      8
#define CTAS     (148 * OCC)          // persistent
#define SF4      264                  // float4s per stage buffer (1056 floats >= 1040 needed)

// XOR swizzle at float4 granularity: makes both the coalesced writes and the
// stride-2-float4 window reads 4-phase (crossbar minimum) in smem.
__device__ __forceinline__ int swz(int v) { return v ^ ((v >> 3) & 7); }

// ---- f32x2 packed helpers (sm_100+) ----
__device__ __forceinline__ uint64_t pack2(float lo, float hi) {
    uint64_t r; asm("mov.b64 %0, {%1, %2};" : "=l"(r) : "f"(lo), "f"(hi)); return r;
}
__device__ __forceinline__ uint64_t dup2(float v) { return pack2(v, v); }
__device__ __forceinline__ void unpack2(uint64_t v, float& lo, float& hi) {
    asm("mov.b64 {%0, %1}, %2;" : "=f"(lo), "=f"(hi) : "l"(v));
}
__device__ __forceinline__ uint64_t fma2(uint64_t a, uint64_t b, uint64_t c) {
    uint64_t d; asm("fma.rn.f32x2 %0, %1, %2, %3;" : "=l"(d) : "l"(a), "l"(b), "l"(c)); return d;
}
__device__ __forceinline__ uint64_t mul2(uint64_t a, uint64_t b) {
    uint64_t d; asm("mul.rn.f32x2 %0, %1, %2;" : "=l"(d) : "l"(a), "l"(b)); return d;
}

__device__ __forceinline__ float4 ldg_f4_clamped(const float* __restrict__ xr, int j0) {
    float t[4];
#pragma unroll
    for (int u = 0; u < 4; ++u) {
        int gi = j0 + u;
        gi = max(0, min(gi, LROW - 1));
        t[u] = __ldg(xr + gi);
    }
    return make_float4(t[0], t[1], t[2], t[3]);
}

// Fused up-2x (12-tap polyphase) -> LeakyReLU(0.1) -> down-2x, f32x2-packed.
// Persistent CTAs; tile window staged via swizzled smem (double-buffered,
// one barrier/tile); next tile's LDGs issue before compute, STS after.
__global__ __launch_bounds__(NTHREADS, OCC)
void aa_act_kernel(const float* __restrict__ x,
                   const float* __restrict__ upf,
                   const float* __restrict__ dnf,
                   float* __restrict__ out,
                   int total_tiles)
{
    __shared__ __align__(16) float4 sbuf[2][SF4];

    // Packed taps (uniform, once per CTA lifetime).
    uint64_t f2[6], dnp[6];
#pragma unroll
    for (int e = 0; e < 6; ++e)
        f2[e] = pack2(2.0f * __ldg(upf + 2 * e), 2.0f * __ldg(upf + 2 * e + 1));
#pragma unroll
    for (int m = 0; m < 6; ++m)
        dnp[m] = pack2(__ldg(dnf + 2 * m + 1), __ldg(dnf + 2 * m));
    const uint64_t c55 = dup2(0.55f), c45 = dup2(0.45f);

    const int tid = threadIdx.x;
    // Swizzled smem addresses are tile-invariant: precompute once.
    int rv[6];
#pragma unroll
    for (int k = 0; k < 6; ++k) rv[k] = swz(2 * tid + k);
    const int w0 = swz(tid), w1 = swz(tid + 128), w2 = swz(tid + 256);

    int tile = blockIdx.x;
    if (tile >= total_tiles) return;

    // Stage one tile's window x[o0-8 .. o0+1047] into registers (clamped at row ends).
    auto ldg_stage = [&](int t_, float4& a, float4& b, float4& c) {
        const int tpos = t_ & (NTILES - 1);
        const int o0   = tpos * TILE;
        const float* xr = x + (size_t)(t_ >> 5) * LROW;
        if ((tpos != 0) & (tpos != NTILES - 1)) {
            const float4* p = (const float4*)(xr + (o0 - 8));   // 16B aligned
            a = __ldg(p + tid);
            b = __ldg(p + tid + 128);
            if (tid < 8) c = __ldg(p + tid + 256);
        } else {
            a = ldg_f4_clamped(xr, o0 - 8 + 4 * tid);
            b = ldg_f4_clamped(xr, o0 - 8 + 4 * (tid + 128));
            if (tid < 8) c = ldg_f4_clamped(xr, o0 - 8 + 4 * (tid + 256));
        }
    };
    auto sts_stage = [&](int b_, const float4& a, const float4& bb, const float4& c) {
        sbuf[b_][w0] = a;
        sbuf[b_][w1] = bb;
        if (tid < 8) sbuf[b_][w2] = c;
    };

    {   // prologue: fill buffer 0
        float4 a, b, c;
        ldg_stage(tile, a, b, c);
        sts_stage(0, a, b, c);
    }
    __syncthreads();

    int buf = 0;
    for (; tile < total_tiles; tile += CTAS) {
        // Issue next tile's global loads first (latency hidden behind compute).
        const int ntile = tile + CTAS;
        const bool have_next = ntile < total_tiles;
        float4 na, nb, nc;
        if (have_next) ldg_stage(ntile, na, nb, nc);

        const int row = tile >> 5;
        const int o   = (tile & (NTILES - 1)) * TILE + tid * CHUNK;

        // Window x[o-8 .. o+15] from swizzled smem -> lane-duplicated packs.
        uint64_t xx[24];
#pragma unroll
        for (int k = 0; k < 6; ++k) {
            float4 q = sbuf[buf][rv[k]];
            xx[4 * k + 0] = dup2(q.x); xx[4 * k + 1] = dup2(q.y);
            xx[4 * k + 2] = dup2(q.z); xx[4 * k + 3] = dup2(q.w);
        }

        // Up-sample + lrelu, packed.  EO[t] = (E[t], O[t]),
        //   E[t]==act[2*(o-2+t)], O[t]==act[2*(o-3+t)+1]; window xx[t+3 .. t+8].
        uint64_t EO[13];
#pragma unroll
        for (int t = 0; t < 13; ++t) {
            uint64_t v = mul2(f2[0], xx[t + 3]);
#pragma unroll
            for (int e = 1; e < 6; ++e)
                v = fma2(f2[e], xx[t + 3 + e], v);
            uint64_t av = v & 0x7FFFFFFF7FFFFFFFULL;      // packed |v|
            EO[t] = fma2(c45, av, mul2(c55, v));          // packed lrelu
        }

        // Row-edge act-index fixups (act index clamps to act[0] / act[2L-1]).
        if (o == 0) {
            float a0 = __uint_as_float((uint32_t)EO[2]);          // E[2]==act[0]
            uint64_t p = dup2(a0);
            EO[0] = p; EO[1] = p; EO[2] = p;
        }
        if (o == LROW - CHUNK) {
            float aL = __uint_as_float((uint32_t)(EO[10] >> 32)); // O[10]==act[2L-1]
            uint64_t p = dup2(aL);
            EO[10] = p; EO[11] = p; EO[12] = p;
        }

        // Downsample: out[o+q] = sum_m dn[2m]*O[q+m] + dn[2m+1]*E[q+m]
        float acc[CHUNK];
#pragma unroll
        for (int q = 0; q < CHUNK; ++q) {
            uint64_t a2 = mul2(dnp[0], EO[q]);
#pragma unroll
            for (int m = 1; m < 6; ++m)
                a2 = fma2(dnp[m], EO[q + m], a2);
            float lo, hi; unpack2(a2, lo, hi);
            acc[q] = lo + hi;
        }

        float4* op = (float4*)(out + (size_t)row * LROW + o);
        op[0] = make_float4(acc[0], acc[1], acc[2], acc[3]);
        op[1] = make_float4(acc[4], acc[5], acc[6], acc[7]);

        // Park next tile's window into the other buffer, then one barrier.
        if (have_next) sts_stage(buf ^ 1, na, nb, nc);
        __syncthreads();
        buf ^= 1;
    }
}

extern "C" void kernel_launch(void* const* d_in, const int* in_sizes, int n_in,
                              void* d_out, int out_size)
{
    const float* x   = (const float*)d_in[0];
    const float* upf = (const float*)d_in[1];
    const float* dnf = (const float*)d_in[2];
    float* out = (float*)d_out;

    const int rows = in_sizes[0] / LROW;           // 8*128 = 1024
    const int total_tiles = rows * NTILES;         // 32768
    aa_act_kernel<<<CTAS, NTHREADS>>>(x, upf, dnf, out, total_tiles);
}